// round 6
// baseline (speedup 1.0000x reference)
#include <cuda_runtime.h>
#include <cuda_fp16.h>

// Problem constants
#define NIMG 256
#define RROOM 32
#define WW 8
#define HH 6
#define MXY 72
#define PIX (MXY*MXY)
#define EMBD 6
#define CIN 16
#define CMID 64

// Scratch (device globals; no allocation allowed).
// Activations stored as channel-paired half2 (unsigned): [n][ch/2][PIX]
__device__ unsigned g_X0h[NIMG*8*PIX];    // 42.5 MB
__device__ unsigned g_XAh[NIMG*32*PIX];   // 170 MB
__device__ unsigned g_XBh[NIMG*32*PIX];   // 170 MB
__device__ float g_feat[NIMG*RROOM*64];
__device__ float g_S[NIMG*128];
__device__ float g_wt[122880];            // transposed FC weights
// packed fp16 conv weights: conv5 @0 (6656), conv3A @6656 (9216), conv3B @15872 (9216)
__device__ uint2 g_wp[25088];

// ---------------------------------------------------------------------------
// helpers
// ---------------------------------------------------------------------------
__device__ __forceinline__ unsigned f2h2(float lo, float hi) {
    __half2 h = __floats2half2_rn(lo, hi);
    return *reinterpret_cast<unsigned*>(&h);
}

__device__ __forceinline__ void mma_f16(float d[4], const unsigned a[4],
                                        unsigned b0, unsigned b1) {
    asm volatile(
        "mma.sync.aligned.m16n8k16.row.col.f32.f16.f16.f32 "
        "{%0,%1,%2,%3},{%4,%5,%6,%7},{%8,%9},{%0,%1,%2,%3};"
        : "+f"(d[0]), "+f"(d[1]), "+f"(d[2]), "+f"(d[3])
        : "r"(a[0]), "r"(a[1]), "r"(a[2]), "r"(a[3]), "r"(b0), "r"(b1));
}

// ---------------------------------------------------------------------------
// one-shot prep: FC transposes + fp16 conv weight packing (mma-ready)
// ---------------------------------------------------------------------------
__global__ void k_prep(const float* __restrict__ w1, const float* __restrict__ w2,
                       const float* __restrict__ w3,
                       const float* __restrict__ wr1, const float* __restrict__ wr2,
                       const float* __restrict__ wf1, const float* __restrict__ wf2,
                       float* __restrict__ wt, uint2* __restrict__ wp) {
    int t0 = blockIdx.x * blockDim.x + threadIdx.x;
    int stride = gridDim.x * blockDim.x;
    for (int i = t0; i < 8192; i += stride)  { int c = i >> 7, o = i & 127; wt[i]         = wr1[o*64 + c]; }
    for (int i = t0; i < 16384; i += stride) { int c = i >> 7, o = i & 127; wt[8192 + i]  = wr2[o*128 + c]; }
    for (int i = t0; i < 32768; i += stride) { int c = i >> 8, o = i & 255; wt[24576 + i] = wf1[o*128 + c]; }
    for (int i = t0; i < 65536; i += stride) { int c = i >> 8, o = i & 255; wt[57344 + i] = wf2[o*256 + c]; }
    // conv5 pack: [cc(2)][ks(13)][o(8)][lane(32)]. chunk = 8 ic; k16 = taps (2ks,2ks+1) x ic-pairs
    for (int i = t0; i < 6656; i += stride) {
        int lane = i & 31, rest = i >> 5;
        int o = rest & 7; rest >>= 3;
        int ks = rest % 13, cc = rest / 13;
        int gg = lane >> 2, tt = lane & 3;
        int oc = o*8 + gg;
        int ic0 = cc*8 + 2*tt;
        int tap0 = 2*ks, tap1 = 2*ks + 1;
        uint2 pv;
        pv.x = f2h2(w1[oc*400 + ic0*25 + tap0], w1[oc*400 + (ic0+1)*25 + tap0]);
        pv.y = (tap1 < 25) ? f2h2(w1[oc*400 + ic0*25 + tap1], w1[oc*400 + (ic0+1)*25 + tap1]) : 0u;
        wp[i] = pv;
    }
    // conv3 packs: [cc(4)][ks(9)][o(8)][lane(32)]. chunk = 16 ic; k16 = one tap x 16 ic
    for (int i = t0; i < 9216; i += stride) {
        int lane = i & 31, rest = i >> 5;
        int o = rest & 7; rest >>= 3;
        int ks = rest % 9, cc = rest / 9;
        int gg = lane >> 2, tt = lane & 3;
        int oc = o*8 + gg;
        int icA = cc*16 + 2*tt;        // k-pair (2tig, 2tig+1)
        int icB = cc*16 + 2*tt + 8;    // k-pair (2tig+8, 2tig+9)
        uint2 pv, qv;
        pv.x = f2h2(w2[oc*576 + icA*9 + ks], w2[oc*576 + (icA+1)*9 + ks]);
        pv.y = f2h2(w2[oc*576 + icB*9 + ks], w2[oc*576 + (icB+1)*9 + ks]);
        wp[6656 + i] = pv;
        qv.x = f2h2(w3[oc*576 + icA*9 + ks], w3[oc*576 + (icA+1)*9 + ks]);
        qv.y = f2h2(w3[oc*576 + icB*9 + ks], w3[oc*576 + (icB+1)*9 + ks]);
        wp[15872 + i] = qv;
    }
}

// ---------------------------------------------------------------------------
// Stage 1: build input X0 (fp16 channel-paired) by GATHER over rooms.
// ---------------------------------------------------------------------------
__global__ void k_build(const int* __restrict__ pos, const float* __restrict__ rt,
                        const float* __restrict__ emb, unsigned* __restrict__ X0h) {
    int n = blockIdx.y;
    int q = blockIdx.x;
    __shared__ int s_px[RROOM], s_py[RROOM];
    __shared__ float s_emb[RROOM*EMBD];
    int t = threadIdx.x;
    if (t < RROOM) { s_px[t] = pos[(n*RROOM+t)*2]; s_py[t] = pos[(n*RROOM+t)*2+1]; }
    if (t < RROOM*EMBD) s_emb[t] = emb[t];
    __syncthreads();
    int p0 = q * 1296, p1 = p0 + 1296;
    for (int pix = p0 + t; pix < p1; pix += blockDim.x) {
        int i = pix / MXY, j = pix % MXY;
        float acc[9];
        float em[EMBD];
        #pragma unroll
        for (int c = 0; c < 9; c++) acc[c] = 0.f;
        #pragma unroll
        for (int e = 0; e < EMBD; e++) em[e] = 0.f;
        #pragma unroll 1
        for (int r = 0; r < RROOM; r++) {
            int w = i - s_px[r], h = j - s_py[r];
            if ((unsigned)w < (unsigned)WW && (unsigned)h < (unsigned)HH) {
                const float* rp = rt + (r*9)*(WW*HH) + w*HH + h;
                float m0 = rp[0];
                #pragma unroll
                for (int c = 0; c < 9; c++) acc[c] += rp[c*(WW*HH)];
                #pragma unroll
                for (int e = 0; e < EMBD; e++) em[e] += s_emb[r*EMBD+e] * m0;
            }
        }
        unsigned* xp = X0h + (size_t)n*8*PIX + pix;
        xp[0*PIX] = f2h2(acc[0], acc[1]);
        xp[1*PIX] = f2h2(acc[2], acc[3]);
        xp[2*PIX] = f2h2(acc[4], acc[5]);
        xp[3*PIX] = f2h2(acc[6], acc[7]);
        xp[4*PIX] = f2h2(acc[8], 1.0f);
        xp[5*PIX] = f2h2(em[0], em[1]);
        xp[6*PIX] = f2h2(em[2], em[3]);
        xp[7*PIX] = f2h2(em[4], em[5]);
    }
}

// ---------------------------------------------------------------------------
// conv3x3 64->64, pad 1, ReLU. fp16 m16n8k16 mma, tap-major K, reg-prefetch
// pipeline. Chunk = 16 ic (8 half2 pairs) x 9 taps = 9 k16-steps; 4 chunks.
// ---------------------------------------------------------------------------
__global__ __launch_bounds__(288, 2)
void k_conv3_mma(const unsigned* __restrict__ in, const uint2* __restrict__ wp,
                 const float* __restrict__ bias, unsigned* __restrict__ out) {
    int tile = blockIdx.x;           // 0..17 row-tile
    int n = blockIdx.y;
    int r0 = tile * 4;
    int t = threadIdx.x;
    int warp = t >> 5, lane = t & 31;
    int g = lane >> 2, tig = lane & 3;

    __shared__ unsigned s_xh[8][6][76];  // pair stride 456 words (456%32==8)
    __shared__ uint2 s_wf[2304];         // [ks][o][lane]

    float acc[2][8][4];
    #pragma unroll
    for (int a = 0; a < 2; a++)
        #pragma unroll
        for (int o = 0; o < 8; o++)
            #pragma unroll
            for (int k = 0; k < 4; k++) acc[a][o][k] = 0.f;

    int prow[2][2], pcol[2][2];
    unsigned axoff[2][2];
    #pragma unroll
    for (int t2 = 0; t2 < 2; t2++)
        #pragma unroll
        for (int gi = 0; gi < 2; gi++) {
            int p = warp*32 + t2*16 + g + gi*8;   // 0..287
            prow[t2][gi] = p / 72;
            pcol[t2][gi] = p % 72;
            axoff[t2][gi] = tig*456 + prow[t2][gi]*76 + pcol[t2][gi];
        }
    const unsigned* sx = &s_xh[0][0][0];

    const unsigned* inb = in + (size_t)n * 32 * PIX;

    // hoisted input-loader tuples (2 per thread; 444 slots)
    int li_rr[2], li_cx[2];
    const unsigned* li_p[2];
    bool li_v[2], li_a[2];
    #pragma unroll
    for (int q2 = 0; q2 < 2; q2++) {
        int idx = t + q2*288;
        li_a[q2] = idx < 444;
        int rr = idx / 74, cx = idx % 74;
        int cc2 = cx - 1, gi2 = r0 + rr - 1;
        li_rr[q2] = rr; li_cx[q2] = cx;
        li_v[q2] = li_a[q2] && cc2 >= 0 && cc2 < 72 && gi2 >= 0 && gi2 < 72;
        li_p[q2] = li_v[q2] ? (inb + gi2*72 + cc2) : inb;
    }

    unsigned pinv[2][8];
    uint2 pw[8];

    // ---- prologue: chunk 0 (pairs 0..7) ----
    #pragma unroll
    for (int j = 0; j < 8; j++) pw[j] = wp[t + j*288];
    #pragma unroll
    for (int q2 = 0; q2 < 2; q2++)
        #pragma unroll
        for (int c = 0; c < 8; c++)
            pinv[q2][c] = li_v[q2] ? __ldg(li_p[q2] + (size_t)c * PIX) : 0u;
    #pragma unroll
    for (int j = 0; j < 8; j++) s_wf[t + j*288] = pw[j];
    #pragma unroll
    for (int q2 = 0; q2 < 2; q2++)
        if (li_a[q2]) {
            #pragma unroll
            for (int c = 0; c < 8; c++)
                s_xh[c][li_rr[q2]][li_cx[q2]] = pinv[q2][c];
        }
    __syncthreads();

    for (int cc = 0; cc < 4; cc++) {
        bool more = cc < 3;
        if (more) {
            const uint2* wpn = wp + (cc+1)*2304;
            #pragma unroll
            for (int j = 0; j < 8; j++) pw[j] = wpn[t + j*288];
            int p0 = (cc+1)*8;
            #pragma unroll
            for (int q2 = 0; q2 < 2; q2++)
                #pragma unroll
                for (int c = 0; c < 8; c++)
                    pinv[q2][c] = li_v[q2] ? __ldg(li_p[q2] + (size_t)(p0+c) * PIX) : 0u;
        }
        // ---- compute chunk cc: 9 k16-steps ----
        #pragma unroll
        for (int ks = 0; ks < 9; ks++) {
            const int off = (ks/3)*76 + (ks%3);
            unsigned av[2][4];
            #pragma unroll
            for (int t2 = 0; t2 < 2; t2++)
                #pragma unroll
                for (int gi = 0; gi < 2; gi++) {
                    av[t2][gi]     = sx[axoff[t2][gi] + off];           // pair tig
                    av[t2][2 + gi] = sx[axoff[t2][gi] + 4*456 + off];   // pair tig+4
                }
            #pragma unroll
            for (int o = 0; o < 8; o++) {
                uint2 b = s_wf[ks*256 + o*32 + lane];
                mma_f16(acc[0][o], av[0], b.x, b.y);
                mma_f16(acc[1][o], av[1], b.x, b.y);
            }
        }
        __syncthreads();
        if (more) {
            #pragma unroll
            for (int j = 0; j < 8; j++) s_wf[t + j*288] = pw[j];
            #pragma unroll
            for (int q2 = 0; q2 < 2; q2++)
                if (li_a[q2]) {
                    #pragma unroll
                    for (int c = 0; c < 8; c++)
                        s_xh[c][li_rr[q2]][li_cx[q2]] = pinv[q2][c];
                }
            __syncthreads();
        }
    }

    // ---- epilogue: bias + ReLU, channel-paired half2 store ----
    unsigned* outb = out + (size_t)n * 32 * PIX;
    #pragma unroll
    for (int o = 0; o < 8; o++) {
        int oc0 = o*8 + 2*tig;
        float bv0 = bias[oc0], bv1 = bias[oc0 + 1];
        #pragma unroll
        for (int t2 = 0; t2 < 2; t2++) {
            #pragma unroll
            for (int gi = 0; gi < 2; gi++) {
                int gr = r0 + prow[t2][gi];
                int gc = pcol[t2][gi];
                float v0 = fmaxf(acc[t2][o][gi*2 + 0] + bv0, 0.f);
                float v1 = fmaxf(acc[t2][o][gi*2 + 1] + bv1, 0.f);
                outb[(size_t)(o*4 + tig) * PIX + gr*72 + gc] = f2h2(v0, v1);
            }
        }
    }
}

// ---------------------------------------------------------------------------
// conv5x5 16->64, pad 2, ReLU. fp16 m16n8k16. Chunk = 8 ic (4 pairs);
// k16-step = taps (2ks,2ks+1) x 8 ic; 13 steps (tap 25 zero-padded); 2 chunks.
// ---------------------------------------------------------------------------
__global__ __launch_bounds__(288, 2)
void k_conv5_mma(const unsigned* __restrict__ in, const uint2* __restrict__ wp,
                 const float* __restrict__ bias, unsigned* __restrict__ out) {
    int tile = blockIdx.x;
    int n = blockIdx.y;
    int r0 = tile * 4;
    int t = threadIdx.x;
    int warp = t >> 5, lane = t & 31;
    int g = lane >> 2, tig = lane & 3;

    __shared__ unsigned s_xh[4][8][77];  // pair stride 616 (616%32==8)
    __shared__ uint2 s_wf[3328];         // [ks(13)][o][lane]

    float acc[2][8][4];
    #pragma unroll
    for (int a = 0; a < 2; a++)
        #pragma unroll
        for (int o = 0; o < 8; o++)
            #pragma unroll
            for (int k = 0; k < 4; k++) acc[a][o][k] = 0.f;

    int prow[2][2], pcol[2][2];
    unsigned axoff[2][2];
    #pragma unroll
    for (int t2 = 0; t2 < 2; t2++)
        #pragma unroll
        for (int gi = 0; gi < 2; gi++) {
            int p = warp*32 + t2*16 + g + gi*8;
            prow[t2][gi] = p / 72;
            pcol[t2][gi] = p % 72;
            axoff[t2][gi] = tig*616 + prow[t2][gi]*77 + pcol[t2][gi];
        }
    const unsigned* sx = &s_xh[0][0][0];

    const unsigned* inb = in + (size_t)n * 8 * PIX;

    // loader tuples: 608 slots = 8 rows x 76 cols; 3 per thread
    int li_rr[3], li_cx[3];
    const unsigned* li_p[3];
    bool li_v[3], li_a[3];
    #pragma unroll
    for (int q2 = 0; q2 < 3; q2++) {
        int idx = t + q2*288;
        li_a[q2] = idx < 608;
        int rr = idx / 76, cx = idx % 76;
        int cc2 = cx - 2, gi2 = r0 + rr - 2;
        li_rr[q2] = rr; li_cx[q2] = cx;
        li_v[q2] = li_a[q2] && cc2 >= 0 && cc2 < 72 && gi2 >= 0 && gi2 < 72;
        li_p[q2] = li_v[q2] ? (inb + gi2*72 + cc2) : inb;
    }

    unsigned pinv[3][4];

    // prologue: chunk 0 (pairs 0..3)
    #pragma unroll
    for (int q2 = 0; q2 < 3; q2++)
        #pragma unroll
        for (int c = 0; c < 4; c++)
            pinv[q2][c] = li_v[q2] ? __ldg(li_p[q2] + (size_t)c * PIX) : 0u;
    #pragma unroll
    for (int j = 0; j < 12; j++) {
        int idx = t + j*288;
        if (idx < 3328) s_wf[idx] = wp[idx];
    }
    #pragma unroll
    for (int q2 = 0; q2 < 3; q2++)
        if (li_a[q2]) {
            #pragma unroll
            for (int c = 0; c < 4; c++)
                s_xh[c][li_rr[q2]][li_cx[q2]] = pinv[q2][c];
        }
    __syncthreads();

    for (int cc = 0; cc < 2; cc++) {
        bool more = cc < 1;
        if (more) {
            #pragma unroll
            for (int q2 = 0; q2 < 3; q2++)
                #pragma unroll
                for (int c = 0; c < 4; c++)
                    pinv[q2][c] = li_v[q2] ? __ldg(li_p[q2] + (size_t)(4+c) * PIX) : 0u;
        }
        #pragma unroll
        for (int ks = 0; ks < 13; ks++) {
            const int tap0 = 2*ks;
            const int tap1 = (2*ks + 1 < 25) ? (2*ks + 1) : 24;  // B zero at pad
            const int off0 = (tap0/5)*77 + (tap0%5);
            const int off1 = (tap1/5)*77 + (tap1%5);
            unsigned av[2][4];
            #pragma unroll
            for (int t2 = 0; t2 < 2; t2++)
                #pragma unroll
                for (int gi = 0; gi < 2; gi++) {
                    av[t2][gi]     = sx[axoff[t2][gi] + off0];   // pair tig, tap0
                    av[t2][2 + gi] = sx[axoff[t2][gi] + off1];   // pair tig, tap1
                }
            #pragma unroll
            for (int o = 0; o < 8; o++) {
                uint2 b = s_wf[ks*256 + o*32 + lane];
                mma_f16(acc[0][o], av[0], b.x, b.y);
                mma_f16(acc[1][o], av[1], b.x, b.y);
            }
        }
        __syncthreads();
        if (more) {
            const uint2* wpn = wp + 3328;
            #pragma unroll
            for (int j = 0; j < 12; j++) {
                int idx = t + j*288;
                if (idx < 3328) s_wf[idx] = wpn[idx];
            }
            #pragma unroll
            for (int q2 = 0; q2 < 3; q2++)
                if (li_a[q2]) {
                    #pragma unroll
                    for (int c = 0; c < 4; c++)
                        s_xh[c][li_rr[q2]][li_cx[q2]] = pinv[q2][c];
                }
            __syncthreads();
        }
    }

    unsigned* outb = out + (size_t)n * 32 * PIX;
    #pragma unroll
    for (int o = 0; o < 8; o++) {
        int oc0 = o*8 + 2*tig;
        float bv0 = bias[oc0], bv1 = bias[oc0 + 1];
        #pragma unroll
        for (int t2 = 0; t2 < 2; t2++) {
            #pragma unroll
            for (int gi = 0; gi < 2; gi++) {
                int gr = r0 + prow[t2][gi];
                int gc = pcol[t2][gi];
                float v0 = fmaxf(acc[t2][o][gi*2 + 0] + bv0, 0.f);
                float v1 = fmaxf(acc[t2][o][gi*2 + 1] + bv1, 0.f);
                outb[(size_t)(o*4 + tig) * PIX + gr*72 + gc] = f2h2(v0, v1);
            }
        }
    }
}

// ---------------------------------------------------------------------------
// Per-room window pooling (input is channel-paired half2)
// ---------------------------------------------------------------------------
__global__ void k_feat(const unsigned* __restrict__ Xh, const float* __restrict__ rt,
                       const int* __restrict__ pos, float* __restrict__ feat) {
    int b = blockIdx.x;            // n*32 + r
    int n = b >> 5, r = b & 31;
    int c = threadIdx.x;           // 0..63
    __shared__ float s_rm[48];
    if (c < 48) s_rm[c] = rt[r*9*48 + c];   // channel 0 = room_map
    __syncthreads();
    float rsum = 0.f;
    #pragma unroll
    for (int k = 0; k < 48; k++) rsum += s_rm[k];
    int px = pos[b*2], py = pos[b*2+1];
    const unsigned* xp = Xh + ((size_t)n*32 + (c >> 1))*PIX + px*72 + py;
    int hi = c & 1;
    float acc = 0.f;
    #pragma unroll
    for (int w = 0; w < WW; w++)
        #pragma unroll
        for (int h = 0; h < HH; h++) {
            unsigned u = xp[w*72 + h];
            __half2 hv = *reinterpret_cast<const __half2*>(&u);
            float val = hi ? __high2float(hv) : __low2float(hv);
            acc += s_rm[w*HH + h] * val;
        }
    feat[b*64 + c] = acc / rsum;
}

// ---------------------------------------------------------------------------
// Per-room MLP 64->128->128 (ReLU), summed over rooms. 4 rooms per pass.
// ---------------------------------------------------------------------------
__global__ __launch_bounds__(128)
void k_room(const float* __restrict__ feat, const float* __restrict__ wt,
            const float* __restrict__ b1, const float* __restrict__ b2,
            float* __restrict__ S) {
    const float* w1t = wt;          // [64][128]
    const float* w2t = wt + 8192;   // [128][128]
    int n = blockIdx.x;
    int o = threadIdx.x;
    __shared__ float s_f[4][64];
    __shared__ float s_h1[4][128];
    float accS = 0.f;
    float bb1 = b1[o], bb2 = b2[o];
    for (int rg = 0; rg < 8; rg++) {
        #pragma unroll
        for (int i = o; i < 256; i += 128) {
            int r = i >> 6, c = i & 63;
            s_f[r][c] = feat[(n*RROOM + rg*4 + r)*64 + c];
        }
        __syncthreads();
        float a0 = bb1, a1 = bb1, a2 = bb1, a3 = bb1;
        #pragma unroll
        for (int c = 0; c < 64; c++) {
            float wv = w1t[c*128 + o];
            a0 += wv * s_f[0][c]; a1 += wv * s_f[1][c];
            a2 += wv * s_f[2][c]; a3 += wv * s_f[3][c];
        }
        s_h1[0][o] = fmaxf(a0, 0.f); s_h1[1][o] = fmaxf(a1, 0.f);
        s_h1[2][o] = fmaxf(a2, 0.f); s_h1[3][o] = fmaxf(a3, 0.f);
        __syncthreads();
        float z0 = bb2, z1 = bb2, z2 = bb2, z3 = bb2;
        #pragma unroll
        for (int c = 0; c < 128; c++) {
            float wv = w2t[c*128 + o];
            z0 += wv * s_h1[0][c]; z1 += wv * s_h1[1][c];
            z2 += wv * s_h1[2][c]; z3 += wv * s_h1[3][c];
        }
        accS += fmaxf(z0, 0.f) + fmaxf(z1, 0.f) + fmaxf(z2, 0.f) + fmaxf(z3, 0.f);
        __syncthreads();
    }
    S[n*128 + o] = accS;
}

// ---------------------------------------------------------------------------
// FC head: 128->256 ReLU -> 256->256. 4 images per block.
// ---------------------------------------------------------------------------
__global__ __launch_bounds__(256)
void k_fc(const float* __restrict__ S, const float* __restrict__ wt,
          const float* __restrict__ bf1, const float* __restrict__ bf2,
          float* __restrict__ out) {
    const float* wf1t = wt + 24576;  // [128][256]
    const float* wf2t = wt + 57344;  // [256][256]
    int n0 = blockIdx.x * 4;
    int o = threadIdx.x;
    __shared__ float s_in[4][128];
    __shared__ float s_h[4][256];
    #pragma unroll
    for (int i = o; i < 512; i += 256) {
        int q = i >> 7, c = i & 127;
        s_in[q][c] = S[(n0 + q)*128 + c];
    }
    __syncthreads();
    float a0 = bf1[o], a1 = a0, a2 = a0, a3 = a0;
    #pragma unroll
    for (int c = 0; c < 128; c++) {
        float wv = wf1t[c*256 + o];
        a0 += wv * s_in[0][c]; a1 += wv * s_in[1][c];
        a2 += wv * s_in[2][c]; a3 += wv * s_in[3][c];
    }
    s_h[0][o] = fmaxf(a0, 0.f); s_h[1][o] = fmaxf(a1, 0.f);
    s_h[2][o] = fmaxf(a2, 0.f); s_h[3][o] = fmaxf(a3, 0.f);
    __syncthreads();
    float z0 = bf2[o], z1 = z0, z2 = z0, z3 = z0;
    #pragma unroll
    for (int c = 0; c < 256; c++) {
        float wv = wf2t[c*256 + o];
        z0 += wv * s_h[0][c]; z1 += wv * s_h[1][c];
        z2 += wv * s_h[2][c]; z3 += wv * s_h[3][c];
    }
    out[(n0 + 0)*256 + o] = z0;
    out[(n0 + 1)*256 + o] = z1;
    out[(n0 + 2)*256 + o] = z2;
    out[(n0 + 3)*256 + o] = z3;
}

extern "C" void kernel_launch(void* const* d_in, const int* in_sizes, int n_in,
                              void* d_out, int out_size) {
    const int*   pos = (const int*)d_in[0];
    const float* rt  = (const float*)d_in[1];
    const float* emb = (const float*)d_in[2];
    const float* w1  = (const float*)d_in[3];
    const float* b1  = (const float*)d_in[4];
    const float* w2  = (const float*)d_in[5];
    const float* b2  = (const float*)d_in[6];
    const float* w3  = (const float*)d_in[7];
    const float* b3  = (const float*)d_in[8];
    const float* wr1 = (const float*)d_in[9];
    const float* br1 = (const float*)d_in[10];
    const float* wr2 = (const float*)d_in[11];
    const float* br2 = (const float*)d_in[12];
    const float* wf1 = (const float*)d_in[13];
    const float* bf1 = (const float*)d_in[14];
    const float* wf2 = (const float*)d_in[15];
    const float* bf2 = (const float*)d_in[16];
    float* out = (float*)d_out;

    unsigned *X0h, *XAh, *XBh;
    float *feat, *S, *wt;
    uint2 *wpk;
    cudaGetSymbolAddress((void**)&X0h, g_X0h);
    cudaGetSymbolAddress((void**)&XAh, g_XAh);
    cudaGetSymbolAddress((void**)&XBh, g_XBh);
    cudaGetSymbolAddress((void**)&feat, g_feat);
    cudaGetSymbolAddress((void**)&S, g_S);
    cudaGetSymbolAddress((void**)&wt, g_wt);
    cudaGetSymbolAddress((void**)&wpk, g_wp);

    k_prep<<<96, 256>>>(w1, w2, w3, wr1, wr2, wf1, wf2, wt, wpk);
    k_build<<<dim3(4, NIMG), 256>>>(pos, rt, emb, X0h);
    k_conv5_mma<<<dim3(18, NIMG), 288>>>(X0h, wpk, b1, XAh);
    k_conv3_mma<<<dim3(18, NIMG), 288>>>(XAh, wpk + 6656, b2, XBh);
    k_conv3_mma<<<dim3(18, NIMG), 288>>>(XBh, wpk + 15872, b3, XAh);
    k_feat<<<NIMG*RROOM, 64>>>(XAh, rt, pos, feat);
    k_room<<<NIMG, 128>>>(feat, wt, br1, br2, S);
    k_fc<<<NIMG/4, 256>>>(S, wt, bf1, bf2, out);
}

// round 8
// speedup vs baseline: 1.1998x; 1.1998x over previous
#include <cuda_runtime.h>
#include <cuda_fp16.h>
#include <cstdint>

#define NIMG 256
#define RROOM 32
#define WW 8
#define HH 6
#define MXY 72
#define PIX (MXY*MXY)
#define EMBD 6

__device__ __align__(16) unsigned g_X0h[NIMG*8*PIX];
__device__ __align__(16) unsigned g_XAh[NIMG*32*PIX];
__device__ __align__(16) unsigned g_XBh[NIMG*32*PIX];
__device__ float g_feat[NIMG*RROOM*64];
__device__ float g_S[NIMG*128];
__device__ float g_wt[122880];
__device__ __align__(16) uint2 g_wp[25088];  // conv5 @0 (6656), conv3A @6656, conv3B @15872

__device__ __forceinline__ unsigned f2h2(float lo, float hi) {
    __half2 h = __floats2half2_rn(lo, hi);
    return *reinterpret_cast<unsigned*>(&h);
}
__device__ __forceinline__ void mma_f16(float d[4], const unsigned a[4], unsigned b0, unsigned b1) {
    asm volatile("mma.sync.aligned.m16n8k16.row.col.f32.f16.f16.f32 "
        "{%0,%1,%2,%3},{%4,%5,%6,%7},{%8,%9},{%0,%1,%2,%3};"
        : "+f"(d[0]), "+f"(d[1]), "+f"(d[2]), "+f"(d[3])
        : "r"(a[0]), "r"(a[1]), "r"(a[2]), "r"(a[3]), "r"(b0), "r"(b1));
}
__device__ __forceinline__ uint32_t smem_u32(const void* p) {
    uint32_t a;
    asm("{ .reg .u64 t; cvta.to.shared.u64 t, %1; cvt.u32.u64 %0, t; }" : "=r"(a) : "l"(p));
    return a;
}
#define CP_COMMIT() asm volatile("cp.async.commit_group;" ::: "memory")
#define CP_WAIT0()  asm volatile("cp.async.wait_group 0;" ::: "memory")

// ---------------- prep (unchanged from passing round-5) ----------------
__global__ void k_prep(const float* __restrict__ w1, const float* __restrict__ w2,
                       const float* __restrict__ w3,
                       const float* __restrict__ wr1, const float* __restrict__ wr2,
                       const float* __restrict__ wf1, const float* __restrict__ wf2,
                       float* __restrict__ wt, uint2* __restrict__ wp) {
    int t0 = blockIdx.x * blockDim.x + threadIdx.x;
    int stride = gridDim.x * blockDim.x;
    for (int i = t0; i < 8192; i += stride)  { int c = i >> 7, o = i & 127; wt[i]         = wr1[o*64 + c]; }
    for (int i = t0; i < 16384; i += stride) { int c = i >> 7, o = i & 127; wt[8192 + i]  = wr2[o*128 + c]; }
    for (int i = t0; i < 32768; i += stride) { int c = i >> 8, o = i & 255; wt[24576 + i] = wf1[o*128 + c]; }
    for (int i = t0; i < 65536; i += stride) { int c = i >> 8, o = i & 255; wt[57344 + i] = wf2[o*256 + c]; }
    for (int i = t0; i < 6656; i += stride) {
        int lane = i & 31, rest = i >> 5;
        int o = rest & 7; rest >>= 3;
        int ks = rest % 13, cc = rest / 13;
        int gg = lane >> 2, tt = lane & 3;
        int oc = o*8 + gg, ic0 = cc*8 + 2*tt;
        int tap0 = 2*ks, tap1 = 2*ks + 1;
        uint2 pv;
        pv.x = f2h2(w1[oc*400 + ic0*25 + tap0], w1[oc*400 + (ic0+1)*25 + tap0]);
        pv.y = (tap1 < 25) ? f2h2(w1[oc*400 + ic0*25 + tap1], w1[oc*400 + (ic0+1)*25 + tap1]) : 0u;
        wp[i] = pv;
    }
    for (int i = t0; i < 9216; i += stride) {
        int lane = i & 31, rest = i >> 5;
        int o = rest & 7; rest >>= 3;
        int ks = rest % 9, cc = rest / 9;
        int gg = lane >> 2, tt = lane & 3;
        int oc = o*8 + gg;
        int icA = cc*16 + 2*tt, icB = cc*16 + 2*tt + 8;
        uint2 pv, qv;
        pv.x = f2h2(w2[oc*576 + icA*9 + ks], w2[oc*576 + (icA+1)*9 + ks]);
        pv.y = f2h2(w2[oc*576 + icB*9 + ks], w2[oc*576 + (icB+1)*9 + ks]);
        wp[6656 + i] = pv;
        qv.x = f2h2(w3[oc*576 + icA*9 + ks], w3[oc*576 + (icA+1)*9 + ks]);
        qv.y = f2h2(w3[oc*576 + icB*9 + ks], w3[oc*576 + (icB+1)*9 + ks]);
        wp[15872 + i] = qv;
    }
}

__global__ void k_build(const int* __restrict__ pos, const float* __restrict__ rt,
                        const float* __restrict__ emb, unsigned* __restrict__ X0h) {
    int n = blockIdx.y, q = blockIdx.x, t = threadIdx.x;
    __shared__ int s_px[RROOM], s_py[RROOM];
    __shared__ float s_emb[RROOM*EMBD];
    if (t < RROOM) { s_px[t] = pos[(n*RROOM+t)*2]; s_py[t] = pos[(n*RROOM+t)*2+1]; }
    if (t < RROOM*EMBD) s_emb[t] = emb[t];
    __syncthreads();
    int p0 = q * 1296, p1 = p0 + 1296;
    for (int pix = p0 + t; pix < p1; pix += blockDim.x) {
        int i = pix / MXY, j = pix % MXY;
        float acc[9], em[EMBD];
        #pragma unroll
        for (int c = 0; c < 9; c++) acc[c] = 0.f;
        #pragma unroll
        for (int e = 0; e < EMBD; e++) em[e] = 0.f;
        #pragma unroll 1
        for (int r = 0; r < RROOM; r++) {
            int w = i - s_px[r], h = j - s_py[r];
            if ((unsigned)w < (unsigned)WW && (unsigned)h < (unsigned)HH) {
                const float* rp = rt + (r*9)*(WW*HH) + w*HH + h;
                float m0 = rp[0];
                #pragma unroll
                for (int c = 0; c < 9; c++) acc[c] += rp[c*(WW*HH)];
                #pragma unroll
                for (int e = 0; e < EMBD; e++) em[e] += s_emb[r*EMBD+e] * m0;
            }
        }
        unsigned* xp = X0h + (size_t)n*8*PIX + pix;
        xp[0*PIX] = f2h2(acc[0], acc[1]);
        xp[1*PIX] = f2h2(acc[2], acc[3]);
        xp[2*PIX] = f2h2(acc[4], acc[5]);
        xp[3*PIX] = f2h2(acc[6], acc[7]);
        xp[4*PIX] = f2h2(acc[8], 1.0f);
        xp[5*PIX] = f2h2(em[0], em[1]);
        xp[6*PIX] = f2h2(em[2], em[3]);
        xp[7*PIX] = f2h2(em[4], em[5]);
    }
}

// ---------------------------------------------------------------------------
// conv3x3 64->64, ReLU. fp16 mma.sync, 8-row tile, 12 warps x 3 m16-tiles.
// All weights preloaded (73.7KB); input double-buffered via cp.async zfill.
// smem: weights @0, bufA0 @73728, bufA1 @98048. Total 122368.
// ---------------------------------------------------------------------------
#define C3_B0 73728
#define C3_B1 98048
#define C3_TOT 122368
__global__ __launch_bounds__(384, 1)
void k_conv3_v2(const unsigned* __restrict__ in, const uint2* __restrict__ wp,
                const float* __restrict__ bias, unsigned* __restrict__ out) {
    extern __shared__ __align__(16) char smem[];
    uint32_t sb = smem_u32(smem);
    int t = threadIdx.x, warp = t >> 5, lane = t & 31;
    int g = lane >> 2, tig = lane & 3;
    int n = blockIdx.y, r0 = blockIdx.x * 8;
    const uint2* swf = (const uint2*)smem;
    const unsigned* inb = in + (size_t)n * 32 * PIX;

    float acc[3][8][4];
    #pragma unroll
    for (int a = 0; a < 3; a++)
        #pragma unroll
        for (int o = 0; o < 8; o++)
            #pragma unroll
            for (int k = 0; k < 4; k++) acc[a][o][k] = 0.f;

    unsigned axoff[3][2];
    #pragma unroll
    for (int t4 = 0; t4 < 3; t4++)
        #pragma unroll
        for (int gi = 0; gi < 2; gi++) {
            int p = warp*48 + t4*16 + g + gi*8;
            axoff[t4][gi] = tig*760 + (p/72)*76 + (p%72);
        }

    // input chunk loader: 8 pairs x 10 rows x 74 cols -> [pair*760 + rr*76 + cx]
    #define C3_LOAD(cq, abase) do { \
        const unsigned* srcb = inb + (size_t)(cq)*8*PIX; \
        _Pragma("unroll") \
        for (int jj = 0; jj < 16; jj++) { \
            int i = t + jj*384; \
            if (i < 5920) { \
                int pair = i / 740; int s = i - pair*740; \
                int rr = s / 74; int cx = s - rr*74; \
                int gr = r0 - 1 + rr, gc = cx - 1; \
                unsigned v = ((unsigned)gr < 72u && (unsigned)gc < 72u) ? 4u : 0u; \
                const unsigned* gp = srcb + (size_t)pair*PIX + (v ? (gr*72 + gc) : 0); \
                unsigned dst = (abase) + (unsigned)(pair*760 + rr*76 + cx)*4u; \
                asm volatile("cp.async.ca.shared.global [%0], [%1], 4, %2;" \
                             :: "r"(dst), "l"(gp), "r"(v) : "memory"); \
            } \
        } } while (0)

    // prologue: all weights + input chunk 0
    #pragma unroll
    for (int jj = 0; jj < 12; jj++) {
        int i = t + jj*384;  // 4608 total
        unsigned dst = sb + (unsigned)i*16u;
        const char* src = (const char*)wp + (size_t)i*16;
        asm volatile("cp.async.cg.shared.global [%0], [%1], 16;" :: "r"(dst), "l"(src) : "memory");
    }
    C3_LOAD(0, sb + C3_B0);
    CP_COMMIT();
    CP_WAIT0();
    __syncthreads();

    #pragma unroll 1
    for (int cc = 0; cc < 4; cc++) {
        if (cc < 3) {
            C3_LOAD(cc+1, (cc & 1) ? (sb + C3_B0) : (sb + C3_B1));
            CP_COMMIT();
        }
        const unsigned* sx = (const unsigned*)(smem + ((cc & 1) ? C3_B1 : C3_B0));
        const uint2* wfc = swf + cc*2304;
        #pragma unroll
        for (int ks = 0; ks < 9; ks++) {
            const int off = (ks/3)*76 + (ks%3);
            unsigned av[3][4];
            #pragma unroll
            for (int t4 = 0; t4 < 3; t4++)
                #pragma unroll
                for (int gi = 0; gi < 2; gi++) {
                    av[t4][gi]     = sx[axoff[t4][gi] + off];
                    av[t4][2 + gi] = sx[axoff[t4][gi] + 4*760 + off];
                }
            #pragma unroll
            for (int o = 0; o < 8; o++) {
                uint2 b = wfc[ks*256 + o*32 + lane];
                mma_f16(acc[0][o], av[0], b.x, b.y);
                mma_f16(acc[1][o], av[1], b.x, b.y);
                mma_f16(acc[2][o], av[2], b.x, b.y);
            }
        }
        if (cc < 3) {
            CP_WAIT0();
            __syncthreads();
        }
    }

    unsigned* outb = out + (size_t)n * 32 * PIX;
    #pragma unroll
    for (int o = 0; o < 8; o++) {
        int oc0 = o*8 + 2*tig;
        float bv0 = bias[oc0], bv1 = bias[oc0 + 1];
        #pragma unroll
        for (int t4 = 0; t4 < 3; t4++)
            #pragma unroll
            for (int gi = 0; gi < 2; gi++) {
                int p = warp*48 + t4*16 + g + gi*8;
                int gr = r0 + p/72, gc = p%72;
                float v0 = fmaxf(acc[t4][o][gi*2 + 0] + bv0, 0.f);
                float v1 = fmaxf(acc[t4][o][gi*2 + 1] + bv1, 0.f);
                outb[(size_t)(o*4 + tig) * PIX + gr*72 + gc] = f2h2(v0, v1);
            }
    }
    #undef C3_LOAD
}

// ---------------------------------------------------------------------------
// conv5x5 16->64, ReLU. 8-row tile, 12 warps x 3 tiles. Entire input (16 ic)
// + all weights resident: one load phase, zero mid-loop barriers.
// smem: weights @0 (53248), input @53248 (8 pairs x 12 rows x 76). Total 82432.
// ---------------------------------------------------------------------------
#define C5_A 53248
#define C5_TOT 82432
__global__ __launch_bounds__(384, 1)
void k_conv5_v2(const unsigned* __restrict__ in, const uint2* __restrict__ wp,
                const float* __restrict__ bias, unsigned* __restrict__ out) {
    extern __shared__ __align__(16) char smem[];
    uint32_t sb = smem_u32(smem);
    int t = threadIdx.x, warp = t >> 5, lane = t & 31;
    int g = lane >> 2, tig = lane & 3;
    int n = blockIdx.y, r0 = blockIdx.x * 8;
    const uint2* swf = (const uint2*)smem;
    const unsigned* sx = (const unsigned*)(smem + C5_A);
    const unsigned* inb = in + (size_t)n * 8 * PIX;

    float acc[3][8][4];
    #pragma unroll
    for (int a = 0; a < 3; a++)
        #pragma unroll
        for (int o = 0; o < 8; o++)
            #pragma unroll
            for (int k = 0; k < 4; k++) acc[a][o][k] = 0.f;

    unsigned axoff[3][2];
    #pragma unroll
    for (int t4 = 0; t4 < 3; t4++)
        #pragma unroll
        for (int gi = 0; gi < 2; gi++) {
            int p = warp*48 + t4*16 + g + gi*8;
            axoff[t4][gi] = (p/72)*76 + (p%72);
        }

    // weights: 6656 uint2 = 53248B = 3328 x 16B
    #pragma unroll
    for (int jj = 0; jj < 9; jj++) {
        int i = t + jj*384;
        if (i < 3328) {
            unsigned dst = sb + (unsigned)i*16u;
            const char* src = (const char*)wp + (size_t)i*16;
            asm volatile("cp.async.cg.shared.global [%0], [%1], 16;" :: "r"(dst), "l"(src) : "memory");
        }
    }
    // input: 8 pairs x 912 slots (12 rows x 76 cols), halo 2
    #pragma unroll
    for (int jj = 0; jj < 19; jj++) {
        int i = t + jj*384;
        if (i < 7296) {
            int pair = i / 912; int s = i - pair*912;
            int rr = s / 76; int cx = s - rr*76;
            int gr = r0 - 2 + rr, gc = cx - 2;
            unsigned v = ((unsigned)gr < 72u && (unsigned)gc < 72u) ? 4u : 0u;
            const unsigned* gp = inb + (size_t)pair*PIX + (v ? (gr*72 + gc) : 0);
            unsigned dst = sb + C5_A + (unsigned)i*4u;
            asm volatile("cp.async.ca.shared.global [%0], [%1], 4, %2;"
                         :: "r"(dst), "l"(gp), "r"(v) : "memory");
        }
    }
    CP_COMMIT();
    CP_WAIT0();
    __syncthreads();

    #pragma unroll 1
    for (int cc = 0; cc < 2; cc++) {
        const unsigned* sxc = sx + (cc*4 + tig)*912;
        const uint2* wfc = swf + cc*3328;
        #pragma unroll
        for (int ks = 0; ks < 13; ks++) {
            const int tap0 = 2*ks;
            const int tap1 = (2*ks + 1 < 25) ? (2*ks + 1) : 24;  // B zero at pad
            const int off0 = (tap0/5)*76 + (tap0%5);
            const int off1 = (tap1/5)*76 + (tap1%5);
            unsigned av[3][4];
            #pragma unroll
            for (int t4 = 0; t4 < 3; t4++)
                #pragma unroll
                for (int gi = 0; gi < 2; gi++) {
                    av[t4][gi]     = sxc[axoff[t4][gi] + off0];
                    av[t4][2 + gi] = sxc[axoff[t4][gi] + off1];
                }
            #pragma unroll
            for (int o = 0; o < 8; o++) {
                uint2 b = wfc[ks*256 + o*32 + lane];
                mma_f16(acc[0][o], av[0], b.x, b.y);
                mma_f16(acc[1][o], av[1], b.x, b.y);
                mma_f16(acc[2][o], av[2], b.x, b.y);
            }
        }
    }

    unsigned* outb = out + (size_t)n * 32 * PIX;
    #pragma unroll
    for (int o = 0; o < 8; o++) {
        int oc0 = o*8 + 2*tig;
        float bv0 = bias[oc0], bv1 = bias[oc0 + 1];
        #pragma unroll
        for (int t4 = 0; t4 < 3; t4++)
            #pragma unroll
            for (int gi = 0; gi < 2; gi++) {
                int p = warp*48 + t4*16 + g + gi*8;
                int gr = r0 + p/72, gc = p%72;
                float v0 = fmaxf(acc[t4][o][gi*2 + 0] + bv0, 0.f);
                float v1 = fmaxf(acc[t4][o][gi*2 + 1] + bv1, 0.f);
                outb[(size_t)(o*4 + tig) * PIX + gr*72 + gc] = f2h2(v0, v1);
            }
    }
}

__global__ void k_feat(const unsigned* __restrict__ Xh, const float* __restrict__ rt,
                       const int* __restrict__ pos, float* __restrict__ feat) {
    int b = blockIdx.x, n = b >> 5, r = b & 31, c = threadIdx.x;
    __shared__ float s_rm[48];
    if (c < 48) s_rm[c] = rt[r*9*48 + c];
    __syncthreads();
    float rsum = 0.f;
    #pragma unroll
    for (int k = 0; k < 48; k++) rsum += s_rm[k];
    int px = pos[b*2], py = pos[b*2+1];
    const unsigned* xp = Xh + ((size_t)n*32 + (c >> 1))*PIX + px*72 + py;
    int hi = c & 1;
    float acc = 0.f;
    #pragma unroll
    for (int w = 0; w < WW; w++)
        #pragma unroll
        for (int h = 0; h < HH; h++) {
            unsigned u = xp[w*72 + h];
            __half2 hv = *reinterpret_cast<const __half2*>(&u);
            acc += s_rm[w*HH + h] * (hi ? __high2float(hv) : __low2float(hv));
        }
    feat[b*64 + c] = acc / rsum;
}

__global__ __launch_bounds__(128)
void k_room(const float* __restrict__ feat, const float* __restrict__ wt,
            const float* __restrict__ b1, const float* __restrict__ b2,
            float* __restrict__ S) {
    const float* w1t = wt;
    const float* w2t = wt + 8192;
    int n = blockIdx.x, o = threadIdx.x;
    __shared__ float s_f[4][64];
    __shared__ float s_h1[4][128];
    float accS = 0.f;
    float bb1 = b1[o], bb2 = b2[o];
    for (int rg = 0; rg < 8; rg++) {
        #pragma unroll
        for (int i = o; i < 256; i += 128) {
            int r = i >> 6, c = i & 63;
            s_f[r][c] = feat[(n*RROOM + rg*4 + r)*64 + c];
        }
        __syncthreads();
        float a0 = bb1, a1 = bb1, a2 = bb1, a3 = bb1;
        #pragma unroll
        for (int c = 0; c < 64; c++) {
            float wv = w1t[c*128 + o];
            a0 += wv * s_f[0][c]; a1 += wv * s_f[1][c];
            a2 += wv * s_f[2][c]; a3 += wv * s_f[3][c];
        }
        s_h1[0][o] = fmaxf(a0, 0.f); s_h1[1][o] = fmaxf(a1, 0.f);
        s_h1[2][o] = fmaxf(a2, 0.f); s_h1[3][o] = fmaxf(a3, 0.f);
        __syncthreads();
        float z0 = bb2, z1 = bb2, z2 = bb2, z3 = bb2;
        #pragma unroll
        for (int c = 0; c < 128; c++) {
            float wv = w2t[c*128 + o];
            z0 += wv * s_h1[0][c]; z1 += wv * s_h1[1][c];
            z2 += wv * s_h1[2][c]; z3 += wv * s_h1[3][c];
        }
        accS += fmaxf(z0, 0.f) + fmaxf(z1, 0.f) + fmaxf(z2, 0.f) + fmaxf(z3, 0.f);
        __syncthreads();
    }
    S[n*128 + o] = accS;
}

__global__ __launch_bounds__(256)
void k_fc(const float* __restrict__ S, const float* __restrict__ wt,
          const float* __restrict__ bf1, const float* __restrict__ bf2,
          float* __restrict__ out) {
    const float* wf1t = wt + 24576;
    const float* wf2t = wt + 57344;
    int n0 = blockIdx.x * 4, o = threadIdx.x;
    __shared__ float s_in[4][128];
    __shared__ float s_h[4][256];
    #pragma unroll
    for (int i = o; i < 512; i += 256) {
        int q = i >> 7, c = i & 127;
        s_in[q][c] = S[(n0 + q)*128 + c];
    }
    __syncthreads();
    float a0 = bf1[o], a1 = a0, a2 = a0, a3 = a0;
    #pragma unroll
    for (int c = 0; c < 128; c++) {
        float wv = wf1t[c*256 + o];
        a0 += wv * s_in[0][c]; a1 += wv * s_in[1][c];
        a2 += wv * s_in[2][c]; a3 += wv * s_in[3][c];
    }
    s_h[0][o] = fmaxf(a0, 0.f); s_h[1][o] = fmaxf(a1, 0.f);
    s_h[2][o] = fmaxf(a2, 0.f); s_h[3][o] = fmaxf(a3, 0.f);
    __syncthreads();
    float z0 = bf2[o], z1 = z0, z2 = z0, z3 = z0;
    #pragma unroll
    for (int c = 0; c < 256; c++) {
        float wv = wf2t[c*256 + o];
        z0 += wv * s_h[0][c]; z1 += wv * s_h[1][c];
        z2 += wv * s_h[2][c]; z3 += wv * s_h[3][c];
    }
    out[(n0 + 0)*256 + o] = z0;
    out[(n0 + 1)*256 + o] = z1;
    out[(n0 + 2)*256 + o] = z2;
    out[(n0 + 3)*256 + o] = z3;
}

extern "C" void kernel_launch(void* const* d_in, const int* in_sizes, int n_in,
                              void* d_out, int out_size) {
    const int*   pos = (const int*)d_in[0];
    const float* rt  = (const float*)d_in[1];
    const float* emb = (const float*)d_in[2];
    const float* w1  = (const float*)d_in[3];
    const float* b1  = (const float*)d_in[4];
    const float* w2  = (const float*)d_in[5];
    const float* b2  = (const float*)d_in[6];
    const float* w3  = (const float*)d_in[7];
    const float* b3  = (const float*)d_in[8];
    const float* wr1 = (const float*)d_in[9];
    const float* br1 = (const float*)d_in[10];
    const float* wr2 = (const float*)d_in[11];
    const float* br2 = (const float*)d_in[12];
    const float* wf1 = (const float*)d_in[13];
    const float* bf1 = (const float*)d_in[14];
    const float* wf2 = (const float*)d_in[15];
    const float* bf2 = (const float*)d_in[16];
    float* out = (float*)d_out;

    unsigned *X0h, *XAh, *XBh;
    float *feat, *S, *wt;
    uint2 *wpk;
    cudaGetSymbolAddress((void**)&X0h, g_X0h);
    cudaGetSymbolAddress((void**)&XAh, g_XAh);
    cudaGetSymbolAddress((void**)&XBh, g_XBh);
    cudaGetSymbolAddress((void**)&feat, g_feat);
    cudaGetSymbolAddress((void**)&S, g_S);
    cudaGetSymbolAddress((void**)&wt, g_wt);
    cudaGetSymbolAddress((void**)&wpk, g_wp);

    cudaFuncSetAttribute(k_conv3_v2, cudaFuncAttributeMaxDynamicSharedMemorySize, C3_TOT);
    cudaFuncSetAttribute(k_conv5_v2, cudaFuncAttributeMaxDynamicSharedMemorySize, C5_TOT);

    k_prep<<<96, 256>>>(w1, w2, w3, wr1, wr2, wf1, wf2, wt, wpk);
    k_build<<<dim3(4, NIMG), 256>>>(pos, rt, emb, X0h);
    k_conv5_v2<<<dim3(9, NIMG), 384, C5_TOT>>>(X0h, wpk, b1, XAh);
    k_conv3_v2<<<dim3(9, NIMG), 384, C3_TOT>>>(XAh, wpk + 6656, b2, XBh);
    k_conv3_v2<<<dim3(9, NIMG), 384, C3_TOT>>>(XBh, wpk + 15872, b3, XAh);
    k_feat<<<NIMG*RROOM, 64>>>(XAh, rt, pos, feat);
    k_room<<<NIMG, 128>>>(feat, wt, br1, br2, S);
    k_fc<<<NIMG/4, 256>>>(S, wt, bf1, bf2, out);
}